// round 5
// baseline (speedup 1.0000x reference)
#include <cuda_runtime.h>
#include <cuda_bf16.h>

// FeaturesLinear: out[seg] = sum_t (weight[ids[t]] * ratings[t]) + bias
// ids: int32[N], ratings: f32[N], segs: int32[N] (sorted), weight: f32[V,16],
// bias: f32[16], out: f32[batch,16].  N = 819200 (multiple of 512).

#define DIM 16
#define TPT 8                 // tokens per thread
#define TG_STRIDE 528         // 8 tokens * 64B + 16B pad (bank-conflict-free)
#define WARP_SMEM (8 * TG_STRIDE)   // 4224 B per warp
#define WARPS_PER_BLOCK 8

__device__ __forceinline__ void cp_async16(unsigned saddr, const void* gptr) {
    asm volatile("cp.async.cg.shared.global [%0], [%1], 16;\n"
                 :: "r"(saddr), "l"(gptr));
}
__device__ __forceinline__ void cp_commit_wait() {
    asm volatile("cp.async.commit_group;\n");
    asm volatile("cp.async.wait_group 0;\n");
}

__global__ void fl_init_out(float4* __restrict__ out,
                            const float4* __restrict__ bias4,
                            int out_quads) {
    int i = blockIdx.x * blockDim.x + threadIdx.x;
    if (i < out_quads) out[i] = __ldg(&bias4[i & 3]);
}

// Lane layout: slot = lane & 3 (which float4 of the 16-float row),
// tokGroup = lane >> 2 (0..7). Thread handles TPT=8 consecutive tokens;
// a warp covers 64 consecutive tokens. Gathers go through cp.async -> smem
// so in-flight rows cost no registers (MLP = 8 at high occupancy).
__global__ __launch_bounds__(256)
void fl_main(const int*   __restrict__ ids,
             const float* __restrict__ ratings,
             const int*   __restrict__ segs,
             const float* __restrict__ weight,
             float*       __restrict__ out,
             int n) {
    __shared__ __align__(16) char sw[WARPS_PER_BLOCK * WARP_SMEM];

    const int lane        = threadIdx.x & 31;
    const int slot        = lane & 3;
    const int tokGroup    = lane >> 2;
    const int warpInBlock = threadIdx.x >> 5;
    const int warpId      = blockIdx.x * WARPS_PER_BLOCK + warpInBlock;

    const int base = warpId * (8 * TPT) + tokGroup * TPT;
    if (base >= n) return;

    // My private smem strip: 8 tokens x 16B (this thread's slot of each row).
    char* myw = sw + warpInBlock * WARP_SMEM + tokGroup * TG_STRIDE + slot * 16;
    unsigned saddr = (unsigned)__cvta_generic_to_shared(myw);

    // ---- token ids -> fire all 8 gathers immediately (ids die young)
    {
        int4 a = __ldcs((const int4*)(ids + base));
        int4 b = __ldcs((const int4*)(ids + base + 4));
        const float* wbase = weight + (size_t)slot * 4;
        cp_async16(saddr + 0 * 64, wbase + (size_t)a.x * DIM);
        cp_async16(saddr + 1 * 64, wbase + (size_t)a.y * DIM);
        cp_async16(saddr + 2 * 64, wbase + (size_t)a.z * DIM);
        cp_async16(saddr + 3 * 64, wbase + (size_t)a.w * DIM);
        cp_async16(saddr + 4 * 64, wbase + (size_t)b.x * DIM);
        cp_async16(saddr + 5 * 64, wbase + (size_t)b.y * DIM);
        cp_async16(saddr + 6 * 64, wbase + (size_t)b.z * DIM);
        cp_async16(saddr + 7 * 64, wbase + (size_t)b.w * DIM);
    }

    // ---- ratings + segment ids load while gathers are in flight
    float r[TPT]; int sg[TPT];
    {
        float4 c = __ldcs((const float4*)(ratings + base));
        float4 d = __ldcs((const float4*)(ratings + base + 4));
        r[0]=c.x; r[1]=c.y; r[2]=c.z; r[3]=c.w;
        r[4]=d.x; r[5]=d.y; r[6]=d.z; r[7]=d.w;
        int4 e = __ldcs((const int4*)(segs + base));
        int4 f = __ldcs((const int4*)(segs + base + 4));
        sg[0]=e.x; sg[1]=e.y; sg[2]=e.z; sg[3]=e.w;
        sg[4]=f.x; sg[5]=f.y; sg[6]=f.z; sg[7]=f.w;
    }

    cp_commit_wait();   // each thread reads back only its own cp.async data

    // ---- thread-serial accumulation with flush on segment boundary
    float4 acc;
    {
        float4 w0 = *(const float4*)(myw + 0 * 64);
        acc.x = w0.x * r[0]; acc.y = w0.y * r[0];
        acc.z = w0.z * r[0]; acc.w = w0.w * r[0];
    }
    #pragma unroll
    for (int k = 1; k < TPT; k++) {
        float4 w = *(const float4*)(myw + k * 64);
        if (sg[k] != sg[k - 1]) {
            float* o = out + (size_t)sg[k - 1] * DIM + slot * 4;
            atomicAdd(o + 0, acc.x);
            atomicAdd(o + 1, acc.y);
            atomicAdd(o + 2, acc.z);
            atomicAdd(o + 3, acc.w);
            acc.x = acc.y = acc.z = acc.w = 0.f;
        }
        acc.x += w.x * r[k]; acc.y += w.y * r[k];
        acc.z += w.z * r[k]; acc.w += w.w * r[k];
    }

    // ---- cross-lane segmented suffix reduction on trailing partials.
    // Trailing keys are monotone across the warp (sorted segs), so the
    // strided conditional add is an exact segmented reduction.
    int seg = sg[TPT - 1];
    #pragma unroll
    for (int off = 4; off <= 16; off <<= 1) {
        int   oseg = __shfl_down_sync(0xffffffffu, seg, off);
        float ox   = __shfl_down_sync(0xffffffffu, acc.x, off);
        float oy   = __shfl_down_sync(0xffffffffu, acc.y, off);
        float oz   = __shfl_down_sync(0xffffffffu, acc.z, off);
        float ow   = __shfl_down_sync(0xffffffffu, acc.w, off);
        if ((lane + off) < 32 && oseg == seg) {
            acc.x += ox; acc.y += oy; acc.z += oz; acc.w += ow;
        }
    }

    const int  pseg = __shfl_up_sync(0xffffffffu, seg, 4);
    const bool head = (tokGroup == 0) || (pseg != seg);

    if (head) {
        float* o = out + (size_t)seg * DIM + slot * 4;
        atomicAdd(o + 0, acc.x);
        atomicAdd(o + 1, acc.y);
        atomicAdd(o + 2, acc.z);
        atomicAdd(o + 3, acc.w);
    }
}

extern "C" void kernel_launch(void* const* d_in, const int* in_sizes, int n_in,
                              void* d_out, int out_size) {
    const int*   ids     = (const int*)  d_in[0];
    const float* ratings = (const float*)d_in[1];
    const int*   segs    = (const int*)  d_in[2];
    // d_in[3] = batch_size scalar (unused)
    const float* weight  = (const float*)d_in[4];
    const float* bias    = (const float*)d_in[5];
    float*       out     = (float*)d_out;

    const int n = in_sizes[0];

    // Init output with bias (vectorized).
    {
        int quads   = out_size / 4;
        int threads = 256;
        int blocks  = (quads + threads - 1) / threads;
        fl_init_out<<<blocks, threads>>>((float4*)out, (const float4*)bias, quads);
    }

    // Main gather + segmented reduce: 64 tokens per warp, 8 warps per block.
    {
        int tokensPerBlock = WARPS_PER_BLOCK * 8 * TPT;   // 512
        int blocks = (n + tokensPerBlock - 1) / tokensPerBlock;
        fl_main<<<blocks, 256>>>(ids, ratings, segs, weight, out, n);
    }
}